// round 1
// baseline (speedup 1.0000x reference)
#include <cuda_runtime.h>

#define B    2048
#define NC   32
#define M    496
#define H1   64
#define H2   32
#define CLS  10
#define EPS  1e-5f

// Intermediate per-module outputs, transposed: g_ot[m*B + b]
__device__ float g_ot[M * B];

__global__ __launch_bounds__(256) void nam_modules_kernel(
    const float* __restrict__ x,
    const float* __restrict__ W1, const float* __restrict__ b1,
    const float* __restrict__ g1, const float* __restrict__ be1,
    const float* __restrict__ m1, const float* __restrict__ v1,
    const float* __restrict__ W2, const float* __restrict__ b2,
    const float* __restrict__ g2, const float* __restrict__ be2,
    const float* __restrict__ m2, const float* __restrict__ v2,
    const float* __restrict__ W3, const float* __restrict__ b3)
{
    const int m   = blockIdx.x;
    const int tid = threadIdx.x;
    const int b   = blockIdx.y * 256 + tid;

    __shared__ float W2t[H1 * H2];              // [k][o] transposed
    __shared__ float As[H1], Bs[H1], Cs[H1];    // folded layer-1 affine (BN1 fused)
    __shared__ float Ds[H2], Es[H2], W3s[H2];   // folded BN2 + output weights
    __shared__ float b3s;
    __shared__ int   sia, sib;

    if (tid == 0) {
        // m-th pair of combinations(range(32), 2), lexicographic
        int rem = m, i = 0;
        while (rem >= NC - 1 - i) { rem -= NC - 1 - i; i++; }
        sia = i;
        sib = i + 1 + rem;
        b3s = b3[m];
    }
    if (tid < H1) {
        const int o = tid;
        const float s = g1[m*H1 + o] * rsqrtf(v1[m*H1 + o] + EPS);
        As[o] = s * W1[(m*H1 + o)*2 + 0];
        Bs[o] = s * W1[(m*H1 + o)*2 + 1];
        Cs[o] = s * (b1[m*H1 + o] - m1[m*H1 + o]) + be1[m*H1 + o];
    } else if (tid < H1 + H2) {
        const int o = tid - H1;
        const float s = g2[m*H2 + o] * rsqrtf(v2[m*H2 + o] + EPS);
        Ds[o]  = s;
        Es[o]  = s * (b2[m*H2 + o] - m2[m*H2 + o]) + be2[m*H2 + o];
        W3s[o] = W3[m*H2 + o];
    }
    // Load W2[m] (H2 x H1, k fastest) transposed into smem as [k][o]
    #pragma unroll
    for (int r = 0; r < (H1 * H2) / 256; r++) {
        const int idx = tid + r * 256;
        const int o = idx / H1;
        const int k = idx % H1;
        W2t[k * H2 + o] = W2[m * (H2 * H1) + idx];
    }
    __syncthreads();

    const float xa = x[b * NC + sia];
    const float xb = x[b * NC + sib];

    float acc[H2];
    #pragma unroll
    for (int o = 0; o < H2; o++) acc[o] = 0.0f;

    #pragma unroll 4
    for (int k = 0; k < H1; k++) {
        const float h1k = fmaxf(fmaf(As[k], xa, fmaf(Bs[k], xb, Cs[k])), 0.0f);
        const float4* w4 = reinterpret_cast<const float4*>(&W2t[k * H2]);
        #pragma unroll
        for (int o4 = 0; o4 < H2 / 4; o4++) {
            const float4 w = w4[o4];
            acc[o4*4 + 0] = fmaf(w.x, h1k, acc[o4*4 + 0]);
            acc[o4*4 + 1] = fmaf(w.y, h1k, acc[o4*4 + 1]);
            acc[o4*4 + 2] = fmaf(w.z, h1k, acc[o4*4 + 2]);
            acc[o4*4 + 3] = fmaf(w.w, h1k, acc[o4*4 + 3]);
        }
    }

    float res = b3s;
    #pragma unroll
    for (int o = 0; o < H2; o++)
        res += W3s[o] * fmaxf(fmaf(Ds[o], acc[o], Es[o]), 0.0f);

    g_ot[m * B + b] = res;
}

__global__ __launch_bounds__(128) void nam_head_kernel(
    const float* __restrict__ Wout,   // [CLS, M]
    const float* __restrict__ bout,   // [CLS]
    float* __restrict__ out)          // [B, CLS]
{
    __shared__ float Ws[CLS * M];     // 19840 B
    for (int i = threadIdx.x; i < CLS * M; i += blockDim.x) Ws[i] = Wout[i];
    __syncthreads();

    const int b = blockIdx.x * blockDim.x + threadIdx.x;

    float acc[CLS];
    #pragma unroll
    for (int c = 0; c < CLS; c++) acc[c] = bout[c];

    #pragma unroll 4
    for (int mm = 0; mm < M; mm++) {
        const float ov = g_ot[mm * B + b];   // coalesced across threads
        #pragma unroll
        for (int c = 0; c < CLS; c++)
            acc[c] = fmaf(ov, Ws[c * M + mm], acc[c]);
    }
    #pragma unroll
    for (int c = 0; c < CLS; c++) out[b * CLS + c] = acc[c];
}

extern "C" void kernel_launch(void* const* d_in, const int* in_sizes, int n_in,
                              void* d_out, int out_size)
{
    // metadata order: x, pair_idx, W1, b1, g1, be1, m1, v1,
    //                 W2, b2, g2, be2, m2, v2, W3, b3, Wout, bout
    const float* x    = (const float*)d_in[0];
    // d_in[1] = pair_idx — intentionally unused (computed analytically on device)
    const float* W1   = (const float*)d_in[2];
    const float* b1   = (const float*)d_in[3];
    const float* g1   = (const float*)d_in[4];
    const float* be1  = (const float*)d_in[5];
    const float* m1   = (const float*)d_in[6];
    const float* v1   = (const float*)d_in[7];
    const float* W2   = (const float*)d_in[8];
    const float* b2   = (const float*)d_in[9];
    const float* g2   = (const float*)d_in[10];
    const float* be2  = (const float*)d_in[11];
    const float* m2   = (const float*)d_in[12];
    const float* v2   = (const float*)d_in[13];
    const float* W3   = (const float*)d_in[14];
    const float* b3   = (const float*)d_in[15];
    const float* Wout = (const float*)d_in[16];
    const float* bout = (const float*)d_in[17];
    float* out = (float*)d_out;

    dim3 grid1(M, B / 256);
    nam_modules_kernel<<<grid1, 256>>>(x, W1, b1, g1, be1, m1, v1,
                                       W2, b2, g2, be2, m2, v2, W3, b3);
    nam_head_kernel<<<B / 128, 128>>>(Wout, bout, out);
}

// round 2
// speedup vs baseline: 1.1609x; 1.1609x over previous
#include <cuda_runtime.h>

#define B    2048
#define NC   32
#define M    496
#define H1   64
#define H2   32
#define CLS  10
#define EPS  1e-5f

// Intermediate per-module outputs, transposed: g_ot[m*B + b]
__device__ float g_ot[M * B];

typedef unsigned long long u64;

__device__ __forceinline__ void ffma2(u64& d, u64 a, u64 b) {
    asm("fma.rn.f32x2 %0, %1, %2, %0;" : "+l"(d) : "l"(a), "l"(b));
}
__device__ __forceinline__ u64 pack2(float v) {
    u64 r;
    asm("mov.b64 %0, {%1, %1};" : "=l"(r) : "r"(__float_as_uint(v)));
    return r;
}
__device__ __forceinline__ void unpack2(u64 v, float& lo, float& hi) {
    unsigned int a, b;
    asm("mov.b64 {%0, %1}, %2;" : "=r"(a), "=r"(b) : "l"(v));
    lo = __uint_as_float(a);
    hi = __uint_as_float(b);
}

__global__ __launch_bounds__(256) void nam_modules_kernel(
    const float* __restrict__ x,
    const float* __restrict__ W1, const float* __restrict__ b1,
    const float* __restrict__ g1, const float* __restrict__ be1,
    const float* __restrict__ m1, const float* __restrict__ v1,
    const float* __restrict__ W2, const float* __restrict__ b2,
    const float* __restrict__ g2, const float* __restrict__ be2,
    const float* __restrict__ m2, const float* __restrict__ v2,
    const float* __restrict__ W3, const float* __restrict__ b3)
{
    const int m   = blockIdx.x;
    const int tid = threadIdx.x;
    const int b   = blockIdx.y * 256 + tid;

    __shared__ __align__(16) float W2t[H1 * H2];   // [k][o] transposed
    __shared__ float As[H1], Bs[H1], Cs[H1];       // folded layer-1 affine (BN1 fused)
    __shared__ float Ds[H2], Es[H2], W3s[H2];      // folded BN2 + output weights
    __shared__ float b3s;
    __shared__ int   sia, sib;

    if (tid == 0) {
        // m-th pair of combinations(range(32), 2), lexicographic
        int rem = m, i = 0;
        while (rem >= NC - 1 - i) { rem -= NC - 1 - i; i++; }
        sia = i;
        sib = i + 1 + rem;
        b3s = b3[m];
    }
    if (tid < H1) {
        const int o = tid;
        const float s = g1[m*H1 + o] * rsqrtf(v1[m*H1 + o] + EPS);
        As[o] = s * W1[(m*H1 + o)*2 + 0];
        Bs[o] = s * W1[(m*H1 + o)*2 + 1];
        Cs[o] = s * (b1[m*H1 + o] - m1[m*H1 + o]) + be1[m*H1 + o];
    } else if (tid < H1 + H2) {
        const int o = tid - H1;
        const float s = g2[m*H2 + o] * rsqrtf(v2[m*H2 + o] + EPS);
        Ds[o]  = s;
        Es[o]  = s * (b2[m*H2 + o] - m2[m*H2 + o]) + be2[m*H2 + o];
        W3s[o] = W3[m*H2 + o];
    }
    // Load W2[m] (H2 x H1, k fastest) transposed into smem as [k][o]
    #pragma unroll
    for (int r = 0; r < (H1 * H2) / 256; r++) {
        const int idx = tid + r * 256;
        const int o = idx / H1;
        const int k = idx % H1;
        W2t[k * H2 + o] = W2[m * (H2 * H1) + idx];
    }
    __syncthreads();

    const float xa = x[b * NC + sia];
    const float xb = x[b * NC + sib];

    // 16 packed accumulators = 32 fp32 outputs; acc2[j] = outputs (2j, 2j+1)
    u64 acc2[H2 / 2];
    #pragma unroll
    for (int j = 0; j < H2 / 2; j++) acc2[j] = 0ull;

    #pragma unroll 8
    for (int k = 0; k < H1; k++) {
        const float h1k = fmaxf(fmaf(As[k], xa, fmaf(Bs[k], xb, Cs[k])), 0.0f);
        const u64 hp = pack2(h1k);
        const ulonglong2* w2 = reinterpret_cast<const ulonglong2*>(&W2t[k * H2]);
        #pragma unroll
        for (int j = 0; j < H2 / 4; j++) {       // 8 x LDS.128 = 16 u64 = 32 floats
            const ulonglong2 w = w2[j];
            ffma2(acc2[2*j + 0], w.x, hp);
            ffma2(acc2[2*j + 1], w.y, hp);
        }
    }

    float res = b3s;
    #pragma unroll
    for (int j = 0; j < H2 / 2; j++) {
        float a0, a1;
        unpack2(acc2[j], a0, a1);
        res += W3s[2*j + 0] * fmaxf(fmaf(Ds[2*j + 0], a0, Es[2*j + 0]), 0.0f);
        res += W3s[2*j + 1] * fmaxf(fmaf(Ds[2*j + 1], a1, Es[2*j + 1]), 0.0f);
    }

    g_ot[m * B + b] = res;
}

// One thread per (b, c) output element: grid (B/256, CLS).
__global__ __launch_bounds__(256) void nam_head_kernel(
    const float* __restrict__ Wout,   // [CLS, M]
    const float* __restrict__ bout,   // [CLS]
    float* __restrict__ out)          // [B, CLS]
{
    const int c = blockIdx.y;
    const int b = blockIdx.x * 256 + threadIdx.x;

    const float* __restrict__ wrow = Wout + c * M;

    float acc = bout[c];
    #pragma unroll 8
    for (int mm = 0; mm < M; mm++) {
        acc = fmaf(g_ot[mm * B + b], __ldg(&wrow[mm]), acc);
    }
    out[b * CLS + c] = acc;
}

extern "C" void kernel_launch(void* const* d_in, const int* in_sizes, int n_in,
                              void* d_out, int out_size)
{
    // metadata order: x, pair_idx, W1, b1, g1, be1, m1, v1,
    //                 W2, b2, g2, be2, m2, v2, W3, b3, Wout, bout
    const float* x    = (const float*)d_in[0];
    // d_in[1] = pair_idx — intentionally unused (computed analytically on device)
    const float* W1   = (const float*)d_in[2];
    const float* b1   = (const float*)d_in[3];
    const float* g1   = (const float*)d_in[4];
    const float* be1  = (const float*)d_in[5];
    const float* m1   = (const float*)d_in[6];
    const float* v1   = (const float*)d_in[7];
    const float* W2   = (const float*)d_in[8];
    const float* b2   = (const float*)d_in[9];
    const float* g2   = (const float*)d_in[10];
    const float* be2  = (const float*)d_in[11];
    const float* m2   = (const float*)d_in[12];
    const float* v2   = (const float*)d_in[13];
    const float* W3   = (const float*)d_in[14];
    const float* b3   = (const float*)d_in[15];
    const float* Wout = (const float*)d_in[16];
    const float* bout = (const float*)d_in[17];
    float* out = (float*)d_out;

    dim3 grid1(M, B / 256);
    nam_modules_kernel<<<grid1, 256>>>(x, W1, b1, g1, be1, m1, v1,
                                       W2, b2, g2, be2, m2, v2, W3, b3);
    dim3 grid2(B / 256, CLS);
    nam_head_kernel<<<grid2, 256>>>(Wout, bout, out);
}

// round 3
// speedup vs baseline: 1.2267x; 1.0567x over previous
#include <cuda_runtime.h>

#define B    2048
#define NC   32
#define M    496
#define H1   64
#define H2   32
#define CLS  10
#define EPS  1e-5f
#define MSPLIT 4
#define MCHUNK (M / MSPLIT)   // 124

// Intermediate per-module outputs, transposed: g_ot[m*B + b]
__device__ float g_ot[M * B];

__global__ __launch_bounds__(256) void nam_modules_kernel(
    const float* __restrict__ x,
    const float* __restrict__ W1, const float* __restrict__ b1,
    const float* __restrict__ g1, const float* __restrict__ be1,
    const float* __restrict__ m1, const float* __restrict__ v1,
    const float* __restrict__ W2, const float* __restrict__ b2,
    const float* __restrict__ g2, const float* __restrict__ be2,
    const float* __restrict__ m2, const float* __restrict__ v2,
    const float* __restrict__ W3, const float* __restrict__ b3)
{
    const int m   = blockIdx.x;
    const int tid = threadIdx.x;
    const int b   = blockIdx.y * 256 + tid;

    __shared__ __align__(16) float W2t[H1 * H2];   // [k][o] transposed
    __shared__ float As[H1], Bs[H1], Cs[H1];       // folded layer-1 affine (BN1 fused)
    __shared__ float Ds[H2], Es[H2], W3s[H2];      // folded BN2 + output weights
    __shared__ float b3s;
    __shared__ int   sia, sib;

    if (tid == 0) {
        // m-th pair of combinations(range(32), 2), lexicographic
        int rem = m, i = 0;
        while (rem >= NC - 1 - i) { rem -= NC - 1 - i; i++; }
        sia = i;
        sib = i + 1 + rem;
        b3s = b3[m];
    }
    if (tid < H1) {
        const int o = tid;
        const float s = g1[m*H1 + o] * rsqrtf(v1[m*H1 + o] + EPS);
        As[o] = s * W1[(m*H1 + o)*2 + 0];
        Bs[o] = s * W1[(m*H1 + o)*2 + 1];
        Cs[o] = s * (b1[m*H1 + o] - m1[m*H1 + o]) + be1[m*H1 + o];
    } else if (tid < H1 + H2) {
        const int o = tid - H1;
        const float s = g2[m*H2 + o] * rsqrtf(v2[m*H2 + o] + EPS);
        Ds[o]  = s;
        Es[o]  = s * (b2[m*H2 + o] - m2[m*H2 + o]) + be2[m*H2 + o];
        W3s[o] = W3[m*H2 + o];
    }
    // Load W2[m] (H2 x H1, k fastest) transposed into smem as [k][o]
    #pragma unroll
    for (int r = 0; r < (H1 * H2) / 256; r++) {
        const int idx = tid + r * 256;
        const int o = idx / H1;
        const int k = idx % H1;
        W2t[k * H2 + o] = W2[m * (H2 * H1) + idx];
    }
    __syncthreads();

    const float xa = x[b * NC + sia];
    const float xb = x[b * NC + sib];

    float acc[H2];
    #pragma unroll
    for (int o = 0; o < H2; o++) acc[o] = 0.0f;

    #pragma unroll 4
    for (int k = 0; k < H1; k++) {
        const float h1k = fmaxf(fmaf(As[k], xa, fmaf(Bs[k], xb, Cs[k])), 0.0f);
        const float4* w4 = reinterpret_cast<const float4*>(&W2t[k * H2]);
        #pragma unroll
        for (int o4 = 0; o4 < H2 / 4; o4++) {
            const float4 w = w4[o4];
            acc[o4*4 + 0] = fmaf(w.x, h1k, acc[o4*4 + 0]);
            acc[o4*4 + 1] = fmaf(w.y, h1k, acc[o4*4 + 1]);
            acc[o4*4 + 2] = fmaf(w.z, h1k, acc[o4*4 + 2]);
            acc[o4*4 + 3] = fmaf(w.w, h1k, acc[o4*4 + 3]);
        }
    }

    float res = b3s;
    #pragma unroll
    for (int o = 0; o < H2; o++)
        res += W3s[o] * fmaxf(fmaf(Ds[o], acc[o], Es[o]), 0.0f);

    g_ot[m * B + b] = res;
}

// Initialize out[b][c] = bout[c] (out is poisoned by the harness).
__global__ __launch_bounds__(256) void head_init_kernel(
    const float* __restrict__ bout, float* __restrict__ out)
{
    const int i = blockIdx.x * 256 + threadIdx.x;
    if (i < B * CLS) out[i] = bout[i % CLS];
}

// Head: grid (B/256, CLS, MSPLIT). Each thread sums a 124-m chunk and
// reduces into out via no-return global atomics (REDG.F32).
__global__ __launch_bounds__(256) void nam_head_kernel(
    const float* __restrict__ Wout,   // [CLS, M]
    float* __restrict__ out)          // [B, CLS]
{
    const int c  = blockIdx.y;
    const int b  = blockIdx.x * 256 + threadIdx.x;
    const int m0 = blockIdx.z * MCHUNK;

    const float* __restrict__ wrow = Wout + c * M + m0;
    const float* __restrict__ gcol = g_ot + m0 * B + b;

    float acc = 0.0f;
    #pragma unroll 31
    for (int mm = 0; mm < MCHUNK; mm++) {
        acc = fmaf(gcol[mm * B], __ldg(&wrow[mm]), acc);
    }
    atomicAdd(&out[b * CLS + c], acc);
}

extern "C" void kernel_launch(void* const* d_in, const int* in_sizes, int n_in,
                              void* d_out, int out_size)
{
    // metadata order: x, pair_idx, W1, b1, g1, be1, m1, v1,
    //                 W2, b2, g2, be2, m2, v2, W3, b3, Wout, bout
    const float* x    = (const float*)d_in[0];
    // d_in[1] = pair_idx — intentionally unused (computed analytically on device)
    const float* W1   = (const float*)d_in[2];
    const float* b1   = (const float*)d_in[3];
    const float* g1   = (const float*)d_in[4];
    const float* be1  = (const float*)d_in[5];
    const float* m1   = (const float*)d_in[6];
    const float* v1   = (const float*)d_in[7];
    const float* W2   = (const float*)d_in[8];
    const float* b2   = (const float*)d_in[9];
    const float* g2   = (const float*)d_in[10];
    const float* be2  = (const float*)d_in[11];
    const float* m2   = (const float*)d_in[12];
    const float* v2   = (const float*)d_in[13];
    const float* W3   = (const float*)d_in[14];
    const float* b3   = (const float*)d_in[15];
    const float* Wout = (const float*)d_in[16];
    const float* bout = (const float*)d_in[17];
    float* out = (float*)d_out;

    head_init_kernel<<<(B * CLS + 255) / 256, 256>>>(bout, out);

    dim3 grid1(M, B / 256);
    nam_modules_kernel<<<grid1, 256>>>(x, W1, b1, g1, be1, m1, v1,
                                       W2, b2, g2, be2, m2, v2, W3, b3);

    dim3 grid2(B / 256, CLS, MSPLIT);
    nam_head_kernel<<<grid2, 256>>>(Wout, out);
}